// round 13
// baseline (speedup 1.0000x reference)
#include <cuda_runtime.h>
#include <cstdint>

// out[i, b*O + o] = input[b, i] * exp(weight[i, o]) + bias[i, o]
// I = 512, O = 128, B = 2048. Output fp32, 512 MB -> HBM-write-roofline.
//
// Final form (R8 structure, best measured 74.0us):
//  - exp(weight) hoisted: computed once per CTA, reused across 64 batches.
//  - Each CTA stages a contiguous 32KB output tile in SMEM (STS.128,
//    conflict-free) and drains it with ONE cp.async.bulk SMEM->GMEM
//    (bypasses the 32 B/cyc/SM L1tex global-store path that bound the
//    STG version at 84.5us).
//  - L2::evict_first on the write stream keeps the 4MB input L2-resident.
// Probed and rejected: double-buffered drain (R9: DRAM% flat, barrier
// overhead +2.5us), 16KB tiles @ occ 94% (R10: DRAM% flat). All variants
// plateau at ~6.3TB/s profiled / ~6.9TB/s timed = 86% of spec, matching
// the measured HBM channel-uniformity bound -> memory roofline reached.

#define I_FEATS   512
#define O_FEATS   128
#define BATCH     2048
#define B_PER_CTA 64                         // batches per CTA tile
#define NCHUNK    (BATCH / B_PER_CTA)        // 32
#define ITERS     (B_PER_CTA / 8)            // 8 warps -> 8 batches each
#define TILE_ELEMS (B_PER_CTA * O_FEATS)     // 8192 floats
#define TILE_BYTES (TILE_ELEMS * 4)          // 32 KB

__global__ void __launch_bounds__(256)
linear_nosum_tma_kernel(const float* __restrict__ input,
                        const float* __restrict__ weight,
                        const float* __restrict__ bias,
                        float* __restrict__ out)
{
    __shared__ alignas(128) float buf[TILE_ELEMS];   // 32 KB static

    const int i     = blockIdx.y;            // feature row 0..511
    const int chunk = blockIdx.x;            // batch chunk 0..31
    const int warp  = threadIdx.x >> 5;      // 0..7
    const int lane  = threadIdx.x & 31;      // 0..31
    const int o     = lane << 2;             // output column base

    // Per-row constants: exp(weight[i, o..o+3]) and bias[i, o..o+3]
    const float4 w4 = *reinterpret_cast<const float4*>(weight + i * O_FEATS + o);
    const float4 b4 = *reinterpret_cast<const float4*>(bias   + i * O_FEATS + o);
    const float e0 = expf(w4.x);
    const float e1 = expf(w4.y);
    const float e2 = expf(w4.z);
    const float e3 = expf(w4.w);

    const int b0 = chunk * B_PER_CTA + warp; // this warp's first batch
    const float* __restrict__ in_ptr = input + (size_t)b0 * I_FEATS + i;

    // Front-batch the 8 strided input scalars (MLP=8 hides DRAM latency).
    float xs[ITERS];
#pragma unroll
    for (int k = 0; k < ITERS; k++)
        xs[k] = __ldg(in_ptr + (size_t)(k << 3) * I_FEATS);

    // Fill the SMEM tile: warp writes 512B contiguous per batch (STS.128).
#pragma unroll
    for (int k = 0; k < ITERS; k++) {
        const float x = xs[k];
        float4 r;
        r.x = fmaf(x, e0, b4.x);
        r.y = fmaf(x, e1, b4.y);
        r.z = fmaf(x, e2, b4.z);
        r.w = fmaf(x, e3, b4.w);
        *reinterpret_cast<float4*>(buf + (warp + (k << 3)) * O_FEATS + o) = r;
    }
    __syncthreads();

    // One 32KB bulk TMA store of the contiguous tile (L1-bypass).
    if (threadIdx.x == 0) {
        uint32_t saddr;
        asm("{ .reg .u64 t; cvta.to.shared.u64 t, %1; cvt.u32.u64 %0, t; }"
            : "=r"(saddr) : "l"(buf));
        float* g = out + (size_t)i * ((size_t)BATCH * O_FEATS)
                       + (size_t)chunk * TILE_ELEMS;
        uint64_t pol;
        asm("createpolicy.fractional.L2::evict_first.b64 %0, 1.0;" : "=l"(pol));
        // Order generic-proxy STS (all threads, post-barrier) before the
        // async-proxy bulk read of SMEM.
        asm volatile("fence.proxy.async.shared::cta;" ::: "memory");
        asm volatile(
            "cp.async.bulk.global.shared::cta.bulk_group.L2::cache_hint "
            "[%0], [%1], %2, %3;"
            :: "l"(g), "r"(saddr), "r"((uint32_t)TILE_BYTES), "l"(pol)
            : "memory");
        asm volatile("cp.async.bulk.commit_group;" ::: "memory");
        // Thread 0 holds the CTA alive until the bulk copy has read SMEM
        // (SMEM is released only when ALL threads exit, so the other
        // threads may retire early with no hazard).
        asm volatile("cp.async.bulk.wait_group.read 0;" ::: "memory");
    }
}

extern "C" void kernel_launch(void* const* d_in, const int* in_sizes, int n_in,
                              void* d_out, int out_size)
{
    const float* input  = (const float*)d_in[0];
    const float* weight = (const float*)d_in[1];
    const float* bias   = (const float*)d_in[2];
    float* out = (float*)d_out;

    dim3 grid(NCHUNK, I_FEATS);   // (32, 512) = 16384 CTAs
    dim3 block(256);
    linear_nosum_tma_kernel<<<grid, block>>>(input, weight, bias, out);
}